// round 2
// baseline (speedup 1.0000x reference)
#include <cuda_runtime.h>
#include <cstdint>

#define NPTS 8192
#define NS   2048
#define NK   32
#define NB   4
#define MPB  65536              /* NK*NS per batch */
#define FSZ  (NB*64*MPB)        /* 16.7M floats per feature buffer */

__device__ float g_y0[FSZ];
__device__ float g_t1[FSZ];
__device__ float g_t2[FSZ];
__device__ float g_x1[FSZ];
__device__ float g_nxyz[NB*NS*3];
__device__ int   g_idx[NB*NK*NS];
__device__ float g_ps[256];
__device__ float g_pq[256];
__device__ float g_aff[5*128];

static __device__ __forceinline__ unsigned long long pk2(float lo, float hi){
    unsigned long long r; asm("mov.b64 %0,{%1,%2};" : "=l"(r) : "f"(lo), "f"(hi)); return r;
}
static __device__ __forceinline__ void upk2(unsigned long long v, float& lo, float& hi){
    asm("mov.b64 {%0,%1},%2;" : "=f"(lo), "=f"(hi) : "l"(v));
}
static __device__ __forceinline__ unsigned long long f2fma(unsigned long long a, unsigned long long b, unsigned long long c){
    unsigned long long r; asm("fma.rn.f32x2 %0,%1,%2,%3;" : "=l"(r) : "l"(a), "l"(b), "l"(c)); return r;
}
static __device__ __forceinline__ unsigned long long f2mul(unsigned long long a, unsigned long long b){
    unsigned long long r; asm("mul.rn.f32x2 %0,%1,%2;" : "=l"(r) : "l"(a), "l"(b)); return r;
}
static __device__ __forceinline__ unsigned long long f2add(unsigned long long a, unsigned long long b){
    unsigned long long r; asm("add.rn.f32x2 %0,%1,%2;" : "=l"(r) : "l"(a), "l"(b)); return r;
}
static __device__ __forceinline__ unsigned long long f2sub(unsigned long long a, unsigned long long b){
    unsigned long long r; asm("sub.rn.f32x2 %0,%1,%2;" : "=l"(r) : "l"(a), "l"(b)); return r;
}

// ---------------- FPS: one block per batch ----------------
__global__ __launch_bounds__(1024, 1) void fps_kernel(const float* __restrict__ xyz,
                                                      float* __restrict__ outxyz,
                                                      float* __restrict__ nxyz)
{
    int b = blockIdx.x, tid = threadIdx.x;
    int lane = tid & 31, wid = tid >> 5;
    const float* X = xyz + (size_t)b * 3 * NPTS;
    int n0 = tid * 8;

    unsigned long long x2[4], y2[4], z2[4];
    float dist[8];
#pragma unroll
    for (int p = 0; p < 4; ++p) {
        x2[p] = pk2(X[n0 + 2*p],          X[n0 + 2*p + 1]);
        y2[p] = pk2(X[NPTS + n0 + 2*p],   X[NPTS + n0 + 2*p + 1]);
        z2[p] = pk2(X[2*NPTS + n0 + 2*p], X[2*NPTS + n0 + 2*p + 1]);
        dist[2*p] = 1e10f; dist[2*p + 1] = 1e10f;
    }

    __shared__ float scen[3];
    __shared__ unsigned swm[32];
    __shared__ unsigned sgm;
    __shared__ int swin;

    int far = 0;
    for (int it = 0; it < NS; ++it) {
        if (tid == (far >> 3)) {
            int j = far & 7;
            float fx = 0.f, fy = 0.f, fz = 0.f, a, c;
#pragma unroll
            for (int p = 0; p < 4; ++p) if ((j >> 1) == p) {
                upk2(x2[p], a, c); fx = (j & 1) ? c : a;
                upk2(y2[p], a, c); fy = (j & 1) ? c : a;
                upk2(z2[p], a, c); fz = (j & 1) ? c : a;
            }
            scen[0] = fx; scen[1] = fy; scen[2] = fz;
            outxyz[(b*3 + 0)*NS + it] = fx;
            outxyz[(b*3 + 1)*NS + it] = fy;
            outxyz[(b*3 + 2)*NS + it] = fz;
            nxyz[((size_t)b*NS + it)*3 + 0] = fx;
            nxyz[((size_t)b*NS + it)*3 + 1] = fy;
            nxyz[((size_t)b*NS + it)*3 + 2] = fz;
        }
        __syncthreads();                       // b1: scen valid; prior swin reads done
        if (tid == 0) swin = 0x7fffffff;

        unsigned long long cx2 = pk2(scen[0], scen[0]);
        unsigned long long cy2 = pk2(scen[1], scen[1]);
        unsigned long long cz2 = pk2(scen[2], scen[2]);

        float rm = 0.f;
#pragma unroll
        for (int p = 0; p < 4; ++p) {
            unsigned long long dx = f2sub(x2[p], cx2);
            unsigned long long dy = f2sub(y2[p], cy2);
            unsigned long long dz = f2sub(z2[p], cz2);
            // (dx*dx + dy*dy) + dz*dz  -- lane-wise identical to scalar mul/add rounding
            unsigned long long s = f2add(f2add(f2mul(dx, dx), f2mul(dy, dy)), f2mul(dz, dz));
            float s0, s1; upk2(s, s0, s1);
            dist[2*p]     = fminf(dist[2*p],     s0);
            dist[2*p + 1] = fminf(dist[2*p + 1], s1);
            rm = fmaxf(rm, dist[2*p]);
            rm = fmaxf(rm, dist[2*p + 1]);
        }
        unsigned key = __float_as_uint(rm);    // dists >= 0 -> monotonic as uint
        unsigned wmax = __reduce_max_sync(0xffffffffu, key);
        if (lane == 0) swm[wid] = wmax;
        __syncthreads();                       // b2
        if (wid == 0) {
            unsigned g = __reduce_max_sync(0xffffffffu, swm[lane]);
            if (lane == 0) sgm = g;
        }
        __syncthreads();                       // b3
        unsigned g = sgm;
        if (key == g) {                        // rare: 1-2 threads
            int bj = 7;
#pragma unroll
            for (int j = 7; j >= 0; --j)
                if (__float_as_uint(dist[j]) == g) bj = j;
            atomicMin(&swin, n0 + bj);         // first-occurrence argmax semantics
        }
        __syncthreads();                       // b4
        far = swin;
    }
}

// ---------------- ball query: one warp per center ----------------
__global__ __launch_bounds__(256) void ball_kernel(const float* __restrict__ xyz,
                                                   const float* __restrict__ nxyz,
                                                   int* __restrict__ gidx)
{
    __shared__ int sbuf[8][32];
    int w = threadIdx.x >> 5, lane = threadIdx.x & 31;
    int gid = blockIdx.x * 8 + w;              // B*S = 8192 centers
    int b = gid >> 11, s = gid & 2047;
    const float* X = xyz + (size_t)b * 3 * NPTS;

    float cx = nxyz[gid*3], cy = nxyz[gid*3 + 1], cz = nxyz[gid*3 + 2];
    float cc = __fadd_rn(__fadd_rn(__fmul_rn(cx,cx), __fmul_rn(cy,cy)), __fmul_rn(cz,cz));
    const float R2 = (float)(0.1 * 0.1);

    int cnt = 0;
    for (int base = 0; base < NPTS; base += 32) {
        int n = base + lane;
        float px = X[n], py = X[NPTS + n], pz = X[2*NPTS + n];
        float pp  = __fadd_rn(__fadd_rn(__fmul_rn(px,px), __fmul_rn(py,py)), __fmul_rn(pz,pz));
        float dot = __fadd_rn(__fadd_rn(__fmul_rn(cx,px), __fmul_rn(cy,py)), __fmul_rn(cz,pz));
        float sqr = __fadd_rn(__fadd_rn(cc, pp), -__fmul_rn(2.f, dot));
        bool hit = (sqr <= R2);
        unsigned m = __ballot_sync(0xffffffffu, hit);
        if (m) {
            int rank = cnt + __popc(m & ((1u << lane) - 1u));
            if (hit && rank < 32) sbuf[w][rank] = n;
            cnt += __popc(m);
            if (cnt >= 32) break;
        }
    }
    __syncwarp();
    int first = sbuf[w][0];                    // center always in-radius -> cnt >= 1
    int my = (lane < cnt) ? sbuf[w][lane] : first;
    gidx[((size_t)(b*32 + lane))*2048 + s] = my;
}

// ---------------- gather + center-subtract + concat ----------------
__global__ __launch_bounds__(256) void gather_kernel(const float* __restrict__ xyz,
                                                     const float* __restrict__ pts,
                                                     const int* __restrict__ gidx,
                                                     const float* __restrict__ nxyz,
                                                     float* __restrict__ xin)
{
    int g = blockIdx.x * 256 + threadIdx.x;    // 262144 (b,k,s)
    int s = g & 2047, k = (g >> 11) & 31, b = g >> 16;
    int id = gidx[((size_t)(b*32 + k))*2048 + s];
    const float* X = xyz + (size_t)b * 3 * NPTS;
    const float* P = pts + (size_t)b * 29 * NPTS;
    size_t ob = (size_t)b * 32 * MPB + (size_t)k * 2048 + s;
#pragma unroll
    for (int c = 0; c < 3; ++c)
        xin[ob + (size_t)c * MPB] = X[c*NPTS + id] - nxyz[((size_t)(b*2048 + s))*3 + c];
#pragma unroll
    for (int c = 0; c < 29; ++c)
        xin[ob + (size_t)(3 + c) * MPB] = P[c*NPTS + id];
}

// ---------------- conv: out[b][o][m] = sum_c W[o][c] * act(in[b][c][m]) ----------------
template<int CIN, bool ACT>
__global__ __launch_bounds__(128) void conv_kernel(const float* __restrict__ in,
                                                   const float* __restrict__ W,
                                                   const float* __restrict__ aff,
                                                   float* __restrict__ out)
{
    __shared__ float sW[CIN][64];
    __shared__ float sA[64], sD[64];
    int tid = threadIdx.x;
    for (int i = tid; i < CIN * 64; i += 128)
        sW[i >> 6][i & 63] = W[(i & 63) * CIN + (i >> 6)];
    if (ACT && tid < CIN) { sA[tid] = aff[tid]; sD[tid] = aff[64 + tid]; }
    __syncthreads();

    int b = blockIdx.x >> 9;
    int m = ((blockIdx.x & 511) << 7) + ((tid & 31) << 2);
    int og = (tid >> 5) << 4;                  // 16 outputs per thread
    const float* ip = in + (size_t)b * CIN * MPB + m;

    unsigned long long acc[8][4];
#pragma unroll
    for (int p = 0; p < 8; ++p)
#pragma unroll
        for (int j = 0; j < 4; ++j) acc[p][j] = 0ull;

#pragma unroll 8
    for (int c = 0; c < CIN; ++c) {
        float4 xv = *(const float4*)(ip + (size_t)c * MPB);
        if (ACT) {
            float a = sA[c], d = sD[c];
            xv.x = fmaxf(fmaf(a, xv.x, d), 0.f);
            xv.y = fmaxf(fmaf(a, xv.y, d), 0.f);
            xv.z = fmaxf(fmaf(a, xv.z, d), 0.f);
            xv.w = fmaxf(fmaf(a, xv.w, d), 0.f);
        }
        unsigned long long xp[4] = { pk2(xv.x, xv.x), pk2(xv.y, xv.y),
                                     pk2(xv.z, xv.z), pk2(xv.w, xv.w) };
        const double2* wp = (const double2*)&sW[c][og];
        double2 w0 = wp[0], w1 = wp[1], w2 = wp[2], w3 = wp[3];
        unsigned long long wq[8] = {
            __double_as_longlong(w0.x), __double_as_longlong(w0.y),
            __double_as_longlong(w1.x), __double_as_longlong(w1.y),
            __double_as_longlong(w2.x), __double_as_longlong(w2.y),
            __double_as_longlong(w3.x), __double_as_longlong(w3.y) };
#pragma unroll
        for (int p = 0; p < 8; ++p)
#pragma unroll
            for (int j = 0; j < 4; ++j)
                acc[p][j] = f2fma(wq[p], xp[j], acc[p][j]);
    }

    float* op = out + (size_t)b * 64 * MPB + m;
#pragma unroll
    for (int p = 0; p < 8; ++p)
#pragma unroll
        for (int j = 0; j < 4; ++j) {
            float lo, hi; upk2(acc[p][j], lo, hi);
            op[(size_t)(og + 2*p)     * MPB + j] = lo;
            op[(size_t)(og + 2*p + 1) * MPB + j] = hi;
        }
}

// ---------------- per-channel stats (two-stage, deterministic) ----------------
__global__ __launch_bounds__(256) void stats1_kernel(const float* __restrict__ in,
                                                     float* __restrict__ ps,
                                                     float* __restrict__ pq)
{
    int o = blockIdx.x >> 2, b = blockIdx.x & 3;
    const float4* p = (const float4*)(in + (size_t)(b*64 + o) * MPB);
    float s = 0.f, q = 0.f;
    for (int i = threadIdx.x; i < MPB/4; i += 256) {
        float4 v = p[i];
        s += v.x + v.y + v.z + v.w;
        q += v.x*v.x + v.y*v.y + v.z*v.z + v.w*v.w;
    }
    __shared__ float rs[256], rq[256];
    rs[threadIdx.x] = s; rq[threadIdx.x] = q;
    for (int off = 128; off; off >>= 1) {
        __syncthreads();
        if (threadIdx.x < off) { rs[threadIdx.x] += rs[threadIdx.x + off];
                                 rq[threadIdx.x] += rq[threadIdx.x + off]; }
    }
    if (threadIdx.x == 0) { ps[blockIdx.x] = rs[0]; pq[blockIdx.x] = rq[0]; }
}

__global__ void statsfin_kernel(const float* __restrict__ ps, const float* __restrict__ pq,
                                const float* __restrict__ gam, const float* __restrict__ bet,
                                float* __restrict__ aff)
{
    int o = threadIdx.x;                       // 64 threads
    float s = ps[o*4] + ps[o*4+1] + ps[o*4+2] + ps[o*4+3];
    float q = pq[o*4] + pq[o*4+1] + pq[o*4+2] + pq[o*4+3];
    const float invn = 1.f / (float)(NB * MPB);
    float mean = s * invn;
    float var  = q * invn - mean * mean;
    float a = gam[o] * rsqrtf(var + 1e-5f);
    aff[o] = a;
    aff[64 + o] = bet[o] - a * mean;
}

// ---------------- residual: x1 = relu(aff2(t2) + relu(aff0(y0))) ----------------
__global__ __launch_bounds__(256) void resid_kernel(const float* __restrict__ y0,
                                                    const float* __restrict__ t2,
                                                    const float* __restrict__ aff0,
                                                    const float* __restrict__ aff2,
                                                    float* __restrict__ x1)
{
    size_t i = (size_t)blockIdx.x * 256 + threadIdx.x;   // float4 index, 4.19M
    int c = (int)((i >> 14) & 63);
    float a0 = aff0[c], d0 = aff0[64+c], a2 = aff2[c], d2 = aff2[64+c];
    float4 y = ((const float4*)y0)[i];
    float4 t = ((const float4*)t2)[i];
    float4 r;
    r.x = fmaxf(fmaf(a2, t.x, d2) + fmaxf(fmaf(a0, y.x, d0), 0.f), 0.f);
    r.y = fmaxf(fmaf(a2, t.y, d2) + fmaxf(fmaf(a0, y.y, d0), 0.f), 0.f);
    r.z = fmaxf(fmaf(a2, t.z, d2) + fmaxf(fmaf(a0, y.z, d0), 0.f), 0.f);
    r.w = fmaxf(fmaf(a2, t.w, d2) + fmaxf(fmaf(a0, y.w, d0), 0.f), 0.f);
    ((float4*)x1)[i] = r;
}

// ---------------- final: feat = max_k relu(aff4(t4) + x1) ----------------
__global__ __launch_bounds__(256) void finalmax_kernel(const float* __restrict__ t4,
                                                       const float* __restrict__ x1,
                                                       const float* __restrict__ aff,
                                                       float* __restrict__ outf)
{
    int g = blockIdx.x * 256 + threadIdx.x;    // 524288 = (b,o,s)
    int s = g & 2047, o = (g >> 11) & 63, b = g >> 17;
    float a = aff[o], d = aff[64 + o];
    size_t base = (size_t)(b*64 + o) * MPB + s;
    const float* tp = t4 + base;
    const float* xp = x1 + base;
    float m = -1e30f;
#pragma unroll 8
    for (int k = 0; k < 32; ++k)
        m = fmaxf(m, fmaf(a, tp[(size_t)k*2048], d) + xp[(size_t)k*2048]);
    outf[g] = fmaxf(m, 0.f);                   // max_k relu == relu(max_k)
}

extern "C" void kernel_launch(void* const* d_in, const int* in_sizes, int n_in,
                              void* d_out, int out_size)
{
    (void)in_sizes; (void)n_in; (void)out_size;
    const float* xyz = (const float*)d_in[0];
    const float* pts = (const float*)d_in[1];
    const float* pw  = (const float*)d_in[2];
    const float* pg  = (const float*)d_in[3];
    const float* pb  = (const float*)d_in[4];
    const float* w1  = (const float*)d_in[5];
    const float* g1  = (const float*)d_in[6];
    const float* b1  = (const float*)d_in[7];
    const float* w2  = (const float*)d_in[8];
    const float* g2  = (const float*)d_in[9];
    const float* b2  = (const float*)d_in[10];

    float *y0, *t1, *t2, *x1, *nx, *ps, *pq, *aff; int* gi;
    cudaGetSymbolAddress((void**)&y0,  g_y0);
    cudaGetSymbolAddress((void**)&t1,  g_t1);
    cudaGetSymbolAddress((void**)&t2,  g_t2);
    cudaGetSymbolAddress((void**)&x1,  g_x1);
    cudaGetSymbolAddress((void**)&nx,  g_nxyz);
    cudaGetSymbolAddress((void**)&gi,  g_idx);
    cudaGetSymbolAddress((void**)&ps,  g_ps);
    cudaGetSymbolAddress((void**)&pq,  g_pq);
    cudaGetSymbolAddress((void**)&aff, g_aff);
    float* out = (float*)d_out;

    fps_kernel<<<NB, 1024>>>(xyz, out, nx);
    ball_kernel<<<1024, 256>>>(xyz, nx, gi);
    gather_kernel<<<1024, 256>>>(xyz, pts, gi, nx, t2);

    conv_kernel<32, false><<<2048, 128>>>(t2, pw, nullptr, y0);
    stats1_kernel<<<256, 256>>>(y0, ps, pq);
    statsfin_kernel<<<1, 64>>>(ps, pq, pg, pb, aff);

    conv_kernel<64, true><<<2048, 128>>>(y0, w1, aff, t1);
    stats1_kernel<<<256, 256>>>(t1, ps, pq);
    statsfin_kernel<<<1, 64>>>(ps, pq, g1, b1, aff + 128);

    conv_kernel<64, true><<<2048, 128>>>(t1, w2, aff + 128, t2);
    stats1_kernel<<<256, 256>>>(t2, ps, pq);
    statsfin_kernel<<<1, 64>>>(ps, pq, g2, b2, aff + 256);

    resid_kernel<<<16384, 256>>>(y0, t2, aff, aff + 256, x1);

    conv_kernel<64, false><<<2048, 128>>>(x1, w1 + 4096, nullptr, t1);
    stats1_kernel<<<256, 256>>>(t1, ps, pq);
    statsfin_kernel<<<1, 64>>>(ps, pq, g1 + 64, b1 + 64, aff + 384);

    conv_kernel<64, true><<<2048, 128>>>(t1, w2 + 4096, aff + 384, t2);
    stats1_kernel<<<256, 256>>>(t2, ps, pq);
    statsfin_kernel<<<1, 64>>>(ps, pq, g2 + 64, b2 + 64, aff + 512);

    finalmax_kernel<<<2048, 256>>>(t2, x1, aff + 512, out + NB*3*NS);
}